// round 1
// baseline (speedup 1.0000x reference)
#include <cuda_runtime.h>
#include <cstdint>

// ---------------------------------------------------------------------------
// Problem constants
// ---------------------------------------------------------------------------
#define NPTS   524288
#define LVLS   16
#define TSIZE  524288u
#define TMASK  (TSIZE - 1u)

// floor(16 * 1.5^l) computed exactly
__constant__ float c_res[LVLS] = {
    16.f, 24.f, 36.f, 54.f, 81.f, 121.f, 182.f, 273.f,
    410.f, 615.f, 922.f, 1383.f, 2075.f, 3113.f, 4670.f, 7006.f
};

// ---------------------------------------------------------------------------
// Scratch (device globals; no runtime allocation)
// ---------------------------------------------------------------------------
__device__ float g_enc_s[(size_t)NPTS * 32];
__device__ float g_enc_d[(size_t)NPTS * 32];
__device__ float g_feat [(size_t)NPTS * 128];

// ---------------------------------------------------------------------------
// Hash-grid encode.  D=3 (static, 8 corners) or D=4 (dynamic, 16 corners).
// WHICH selects output buffer: 0 -> g_enc_s, 1 -> g_enc_d.
// ---------------------------------------------------------------------------
template <int D, int WHICH>
__global__ void __launch_bounds__(256)
encode_kernel(const float* __restrict__ x,
              const float* __restrict__ tptr,
              const float* __restrict__ table)
{
    const int n = blockIdx.x * 256 + threadIdx.x;

    float p[4];
    p[0] = x[3 * n + 0];
    p[1] = x[3 * n + 1];
    p[2] = x[3 * n + 2];
    if (D == 4) p[3] = __ldg(tptr);

    float encout[32];

    #pragma unroll
    for (int l = 0; l < LVLS; l++) {
        const float res = c_res[l];
        uint32_t h[4][2];
        float    w[4][2];
        #pragma unroll
        for (int d = 0; d < D; d++) {
            const uint32_t pr = (d == 0) ? 1u
                              : (d == 1) ? 2654435761u
                              : (d == 2) ? 805459861u
                                         : 3674653429u;
            float pos = p[d] * res;
            float p0f = floorf(pos);
            float fr  = pos - p0f;
            uint32_t p0 = (uint32_t)p0f;
            h[d][0] = p0 * pr;
            h[d][1] = (p0 + 1u) * pr;
            w[d][0] = 1.f - fr;
            w[d][1] = fr;
        }

        const float2* tl = (const float2*)table + (size_t)l * TSIZE;
        float f0 = 0.f, f1 = 0.f;
        #pragma unroll
        for (int c = 0; c < (1 << D); c++) {
            uint32_t hh = h[0][c & 1] ^ h[1][(c >> 1) & 1] ^ h[2][(c >> 2) & 1];
            float    ww = w[0][c & 1] * w[1][(c >> 1) & 1] * w[2][(c >> 2) & 1];
            if (D == 4) {
                hh ^= h[3][(c >> 3) & 1];
                ww *= w[3][(c >> 3) & 1];
            }
            float2 f = __ldg(tl + (hh & TMASK));
            f0 = fmaf(ww, f.x, f0);
            f1 = fmaf(ww, f.y, f1);
        }
        encout[2 * l + 0] = f0;
        encout[2 * l + 1] = f1;
    }

    float* dst = (WHICH == 0 ? g_enc_s : g_enc_d) + (size_t)n * 32;
    float4* d4 = (float4*)dst;
    #pragma unroll
    for (int i = 0; i < 8; i++)
        d4[i] = make_float4(encout[4 * i], encout[4 * i + 1],
                            encout[4 * i + 2], encout[4 * i + 3]);
}

// ---------------------------------------------------------------------------
// Dense layer: thread-private activation row in padded smem, accumulators in
// registers, weights staged in smem and read as broadcast LDS.128.
// W is [IN, OUT] row-major: out[j] = sum_i in[i] * W[i*OUT + j]
// ---------------------------------------------------------------------------
template <int IN, int OUT, bool RELU, int NT>
__device__ __forceinline__ void dense(const float* __restrict__ gW,
                                      float* wbuf, float* row)
{
    const int tid = threadIdx.x;
    __syncthreads();                       // protect previous wbuf readers
    {
        const float4* g4 = (const float4*)gW;
        float4* b4 = (float4*)wbuf;
        for (int k = tid; k < IN * OUT / 4; k += NT) b4[k] = g4[k];
    }
    __syncthreads();

    float acc[OUT];
    #pragma unroll
    for (int j = 0; j < OUT; j++) acc[j] = 0.f;

    #pragma unroll 4
    for (int i = 0; i < IN; i++) {
        float a = row[i];
        const float4* w4 = (const float4*)(wbuf + i * OUT);
        #pragma unroll
        for (int j = 0; j < OUT / 4; j++) {
            float4 wv = w4[j];
            acc[4 * j + 0] = fmaf(a, wv.x, acc[4 * j + 0]);
            acc[4 * j + 1] = fmaf(a, wv.y, acc[4 * j + 1]);
            acc[4 * j + 2] = fmaf(a, wv.z, acc[4 * j + 2]);
            acc[4 * j + 3] = fmaf(a, wv.w, acc[4 * j + 3]);
        }
    }

    #pragma unroll
    for (int j = 0; j < OUT; j++)
        row[j] = RELU ? fmaxf(acc[j], 0.f) : acc[j];
}

// ---------------------------------------------------------------------------
// Branch MLP: enc[32] -> 64 (relu) -> 64x3 (relu) -> 64 (linear)
// Writes to g_feat[:, WHICH*64 .. WHICH*64+63]
// smem: act 256*65 floats + wbuf 64*64 floats
// ---------------------------------------------------------------------------
#define MLP64_SMEM ((256 * 65 + 64 * 64) * 4)

template <int WHICH>
__global__ void __launch_bounds__(256)
mlp64_kernel(const float* __restrict__ w_in,
             const float* __restrict__ w_hid,
             const float* __restrict__ w_out)
{
    extern __shared__ float sm[];
    float* act  = sm;                 // 256 * 65
    float* wbuf = sm + 256 * 65;      // 4096

    const int tid = threadIdx.x;
    const size_t n = (size_t)blockIdx.x * 256 + tid;
    float* row = act + tid * 65;

    const float* enc = (WHICH == 0 ? g_enc_s : g_enc_d) + n * 32;
    const float4* e4 = (const float4*)enc;
    #pragma unroll
    for (int i = 0; i < 8; i++) {
        float4 v = e4[i];
        row[4 * i + 0] = v.x; row[4 * i + 1] = v.y;
        row[4 * i + 2] = v.z; row[4 * i + 3] = v.w;
    }

    dense<32, 64, true,  256>(w_in,          wbuf, row);
    dense<64, 64, true,  256>(w_hid + 0,     wbuf, row);
    dense<64, 64, true,  256>(w_hid + 4096,  wbuf, row);
    dense<64, 64, true,  256>(w_hid + 8192,  wbuf, row);
    dense<64, 64, false, 256>(w_out,         wbuf, row);

    float4* f4 = (float4*)(g_feat + n * 128 + WHICH * 64);
    #pragma unroll
    for (int i = 0; i < 16; i++)
        f4[i] = make_float4(row[4 * i], row[4 * i + 1],
                            row[4 * i + 2], row[4 * i + 3]);
}

// ---------------------------------------------------------------------------
// Head: feat[128] -> mlp1(128->64->64->128) -> blend -> mlp2(128->64->64->1)
// smem: act 128*129 floats + wbuf 128*64 floats
// ---------------------------------------------------------------------------
#define HEAD_SMEM ((128 * 129 + 128 * 64) * 4)

__global__ void __launch_bounds__(128)
head_kernel(const float* __restrict__ alpha_p,
            const float* __restrict__ w1_in,
            const float* __restrict__ w1_hid,
            const float* __restrict__ w1_out,
            const float* __restrict__ w2_in,
            const float* __restrict__ w2_hid,
            const float* __restrict__ w2_out,
            float* __restrict__ out)
{
    extern __shared__ float sm[];
    float* act  = sm;                 // 128 * 129
    float* wbuf = sm + 128 * 129;     // 8192

    const int tid = threadIdx.x;
    const size_t n = (size_t)blockIdx.x * 128 + tid;
    float* row = act + tid * 129;

    const float4* f4 = (const float4*)(g_feat + n * 128);
    #pragma unroll
    for (int i = 0; i < 32; i++) {
        float4 v = f4[i];
        row[4 * i + 0] = v.x; row[4 * i + 1] = v.y;
        row[4 * i + 2] = v.z; row[4 * i + 3] = v.w;
    }

    dense<128, 64, true,  128>(w1_in,  wbuf, row);
    dense< 64, 64, true,  128>(w1_hid, wbuf, row);
    dense< 64, 128, false, 128>(w1_out, wbuf, row);

    // blended = out1 * alpha + (1 - alpha) * features
    const float alpha = __ldg(alpha_p);
    const float beta  = 1.f - alpha;
    #pragma unroll
    for (int i = 0; i < 32; i++) {
        float4 v = f4[i];
        row[4 * i + 0] = row[4 * i + 0] * alpha + beta * v.x;
        row[4 * i + 1] = row[4 * i + 1] * alpha + beta * v.y;
        row[4 * i + 2] = row[4 * i + 2] * alpha + beta * v.z;
        row[4 * i + 3] = row[4 * i + 3] * alpha + beta * v.w;
    }

    dense<128, 64, true, 128>(w2_in,  wbuf, row);
    dense< 64, 64, true, 128>(w2_hid, wbuf, row);

    // final 64 -> 1
    __syncthreads();
    for (int k = tid; k < 64; k += 128) wbuf[k] = w2_out[k];
    __syncthreads();
    float acc = 0.f;
    #pragma unroll
    for (int i = 0; i < 64; i++) acc = fmaf(row[i], wbuf[i], acc);
    out[n] = acc;
}

// ---------------------------------------------------------------------------
// Launch
// ---------------------------------------------------------------------------
extern "C" void kernel_launch(void* const* d_in, const int* in_sizes, int n_in,
                              void* d_out, int out_size)
{
    const float* x       = (const float*)d_in[0];
    const float* t       = (const float*)d_in[1];
    const float* alpha   = (const float*)d_in[2];
    const float* table_s = (const float*)d_in[3];
    const float* ws_in   = (const float*)d_in[4];
    const float* ws_hid  = (const float*)d_in[5];
    const float* ws_out  = (const float*)d_in[6];
    const float* table_d = (const float*)d_in[7];
    const float* wd_in   = (const float*)d_in[8];
    const float* wd_hid  = (const float*)d_in[9];
    const float* wd_out  = (const float*)d_in[10];
    const float* w1_in   = (const float*)d_in[11];
    const float* w1_hid  = (const float*)d_in[12];
    const float* w1_out  = (const float*)d_in[13];
    const float* w2_in   = (const float*)d_in[14];
    const float* w2_hid  = (const float*)d_in[15];
    const float* w2_out  = (const float*)d_in[16];
    float* out = (float*)d_out;

    cudaFuncSetAttribute(mlp64_kernel<0>, cudaFuncAttributeMaxDynamicSharedMemorySize, MLP64_SMEM);
    cudaFuncSetAttribute(mlp64_kernel<1>, cudaFuncAttributeMaxDynamicSharedMemorySize, MLP64_SMEM);
    cudaFuncSetAttribute(head_kernel,     cudaFuncAttributeMaxDynamicSharedMemorySize, HEAD_SMEM);

    const int nblk256 = NPTS / 256;
    const int nblk128 = NPTS / 128;

    encode_kernel<3, 0><<<nblk256, 256>>>(x, nullptr, table_s);
    encode_kernel<4, 1><<<nblk256, 256>>>(x, t,       table_d);

    mlp64_kernel<0><<<nblk256, 256, MLP64_SMEM>>>(ws_in, ws_hid, ws_out);
    mlp64_kernel<1><<<nblk256, 256, MLP64_SMEM>>>(wd_in, wd_hid, wd_out);

    head_kernel<<<nblk128, 128, HEAD_SMEM>>>(alpha, w1_in, w1_hid, w1_out,
                                             w2_in, w2_hid, w2_out, out);
}

// round 3
// speedup vs baseline: 1.2502x; 1.2502x over previous
#include <cuda_runtime.h>
#include <cuda_fp16.h>
#include <cstdint>

// ---------------------------------------------------------------------------
// Problem constants
// ---------------------------------------------------------------------------
#define NPTS   524288
#define LVLS   16
#define TSIZE  524288u
#define TMASK  (TSIZE - 1u)

__constant__ float c_res[LVLS] = {
    16.f, 24.f, 36.f, 54.f, 81.f, 121.f, 182.f, 273.f,
    410.f, 615.f, 922.f, 1383.f, 2075.f, 3113.f, 4670.f, 7006.f
};

// ---------------------------------------------------------------------------
// Scratch (device globals; no runtime allocation)
// hi/lo fp16 planes: value = hi + lo (22-bit effective mantissa)
// ---------------------------------------------------------------------------
__device__ __half g_enc_s_hi[(size_t)NPTS * 32];
__device__ __half g_enc_s_lo[(size_t)NPTS * 32];
__device__ __half g_enc_d_hi[(size_t)NPTS * 32];
__device__ __half g_enc_d_lo[(size_t)NPTS * 32];
__device__ __half g_feat_hi [(size_t)NPTS * 128];
__device__ __half g_feat_lo [(size_t)NPTS * 128];

// ---------------------------------------------------------------------------
// hi/lo split helpers
// ---------------------------------------------------------------------------
__device__ __forceinline__ void split2(float x, __half& h, __half& l) {
    h = __float2half_rn(x);
    l = __float2half_rn(x - __half2float(h));
}

// ---------------------------------------------------------------------------
// Hash-grid encode.  D=3 (static) or D=4 (dynamic).
// ---------------------------------------------------------------------------
template <int D, int WHICH>
__global__ void __launch_bounds__(256)
encode_kernel(const float* __restrict__ x,
              const float* __restrict__ tptr,
              const float* __restrict__ table)
{
    const int n = blockIdx.x * 256 + threadIdx.x;

    float p[4];
    p[0] = x[3 * n + 0];
    p[1] = x[3 * n + 1];
    p[2] = x[3 * n + 2];
    if (D == 4) p[3] = __ldg(tptr);

    __half2 ehi[16], elo[16];

    #pragma unroll
    for (int l = 0; l < LVLS; l++) {
        const float res = c_res[l];
        uint32_t h[4][2];
        float    w[4][2];
        #pragma unroll
        for (int d = 0; d < D; d++) {
            const uint32_t pr = (d == 0) ? 1u
                              : (d == 1) ? 2654435761u
                              : (d == 2) ? 805459861u
                                         : 3674653429u;
            float pos = p[d] * res;
            float p0f = floorf(pos);
            float fr  = pos - p0f;
            uint32_t p0 = (uint32_t)p0f;
            h[d][0] = p0 * pr;
            h[d][1] = (p0 + 1u) * pr;
            w[d][0] = 1.f - fr;
            w[d][1] = fr;
        }

        const float2* tl = (const float2*)table + (size_t)l * TSIZE;
        float f0 = 0.f, f1 = 0.f;
        #pragma unroll
        for (int c = 0; c < (1 << D); c++) {
            uint32_t hh = h[0][c & 1] ^ h[1][(c >> 1) & 1] ^ h[2][(c >> 2) & 1];
            float    ww = w[0][c & 1] * w[1][(c >> 1) & 1] * w[2][(c >> 2) & 1];
            if (D == 4) {
                hh ^= h[3][(c >> 3) & 1];
                ww *= w[3][(c >> 3) & 1];
            }
            float2 f = __ldg(tl + (hh & TMASK));
            f0 = fmaf(ww, f.x, f0);
            f1 = fmaf(ww, f.y, f1);
        }
        __half h0, l0, h1, l1;
        split2(f0, h0, l0);
        split2(f1, h1, l1);
        ehi[l] = __halves2half2(h0, h1);
        elo[l] = __halves2half2(l0, l1);
    }

    __half* dh = (WHICH == 0 ? g_enc_s_hi : g_enc_d_hi) + (size_t)n * 32;
    __half* dl = (WHICH == 0 ? g_enc_s_lo : g_enc_d_lo) + (size_t)n * 32;
    #pragma unroll
    for (int i = 0; i < 4; i++) ((uint4*)dh)[i] = ((const uint4*)ehi)[i];
    #pragma unroll
    for (int i = 0; i < 4; i++) ((uint4*)dl)[i] = ((const uint4*)elo)[i];
}

// ---------------------------------------------------------------------------
// Tensor-core helpers
// ---------------------------------------------------------------------------
__device__ __forceinline__ uint32_t smem_u32(const void* p) {
    return (uint32_t)__cvta_generic_to_shared(p);
}

__device__ __forceinline__ void ldsm_x4(uint32_t& r0, uint32_t& r1,
                                        uint32_t& r2, uint32_t& r3, uint32_t a) {
    asm volatile("ldmatrix.sync.aligned.m8n8.x4.shared.b16 {%0,%1,%2,%3}, [%4];"
                 : "=r"(r0), "=r"(r1), "=r"(r2), "=r"(r3) : "r"(a));
}

__device__ __forceinline__ void ldsm_x4_t(uint32_t& r0, uint32_t& r1,
                                          uint32_t& r2, uint32_t& r3, uint32_t a) {
    asm volatile("ldmatrix.sync.aligned.m8n8.x4.trans.shared.b16 {%0,%1,%2,%3}, [%4];"
                 : "=r"(r0), "=r"(r1), "=r"(r2), "=r"(r3) : "r"(a));
}

__device__ __forceinline__ void mma16816(float* c, uint32_t a0, uint32_t a1,
                                         uint32_t a2, uint32_t a3,
                                         uint32_t b0, uint32_t b1) {
    asm volatile(
        "mma.sync.aligned.m16n8k16.row.col.f32.f16.f16.f32 "
        "{%0,%1,%2,%3}, {%4,%5,%6,%7}, {%8,%9}, {%0,%1,%2,%3};"
        : "+f"(c[0]), "+f"(c[1]), "+f"(c[2]), "+f"(c[3])
        : "r"(a0), "r"(a1), "r"(a2), "r"(a3), "r"(b0), "r"(b1));
}

// ---------------------------------------------------------------------------
// Split-fp16 warp GEMM: C = A*W with A,W as (hi,lo) fp16 plane pairs.
//   C = A_hi W_hi + A_hi W_lo + A_lo W_hi  (fp32 accumulate)
// A: warp-private 16 rows, stride sa, lo plane at +apl.
// W: stride ws, lo plane at +wpl.  Dest Bo: stride sb, lo plane at +bpl.
// BLEND: dest element = acc*alpha + beta*(F_hi+F_lo) at same coords (F == Bo).
// Strides in halves; stride/2 must be ≡ 4 (mod 8) for conflict-free ldmatrix.
// ---------------------------------------------------------------------------
template <int KT, int NT, bool RELU, bool BLEND>
__device__ __forceinline__ void gemm_split(const __half* A, int sa, int apl,
                                           const __half* W, int ws, int wpl,
                                           __half* Bo, int sb, int bpl,
                                           const __half* F, int sf, int fpl,
                                           float alpha, float beta)
{
    const int lane = threadIdx.x & 31;
    float acc[NT][4];
    #pragma unroll
    for (int t = 0; t < NT; t++)
        #pragma unroll
        for (int j = 0; j < 4; j++) acc[t][j] = 0.f;

    #pragma unroll
    for (int kk = 0; kk < KT; kk++) {
        const __half* ap = A + (lane & 15) * sa + kk * 16 + ((lane >> 4) << 3);
        uint32_t ah0, ah1, ah2, ah3, al0, al1, al2, al3;
        ldsm_x4(ah0, ah1, ah2, ah3, smem_u32(ap));
        ldsm_x4(al0, al1, al2, al3, smem_u32(ap + apl));
        #pragma unroll
        for (int nb = 0; nb < NT / 2; nb++) {
            const __half* wp = W + (kk * 16 + (lane & 7) + ((lane >> 3) & 1) * 8) * ws
                                 + nb * 16 + ((lane >> 4) << 3);
            uint32_t bh0, bh1, bh2, bh3, bl0, bl1, bl2, bl3;
            ldsm_x4_t(bh0, bh1, bh2, bh3, smem_u32(wp));
            ldsm_x4_t(bl0, bl1, bl2, bl3, smem_u32(wp + wpl));
            mma16816(acc[2 * nb + 0], ah0, ah1, ah2, ah3, bh0, bh1);
            mma16816(acc[2 * nb + 0], ah0, ah1, ah2, ah3, bl0, bl1);
            mma16816(acc[2 * nb + 0], al0, al1, al2, al3, bh0, bh1);
            mma16816(acc[2 * nb + 1], ah0, ah1, ah2, ah3, bh2, bh3);
            mma16816(acc[2 * nb + 1], ah0, ah1, ah2, ah3, bl2, bl3);
            mma16816(acc[2 * nb + 1], al0, al1, al2, al3, bh2, bh3);
        }
    }

    __syncwarp();
    const int r0 = lane >> 2;
    #pragma unroll
    for (int t = 0; t < NT; t++) {
        const int c0 = t * 8 + (lane & 3) * 2;
        float v[4] = { acc[t][0], acc[t][1], acc[t][2], acc[t][3] };
        if (RELU) {
            #pragma unroll
            for (int j = 0; j < 4; j++) v[j] = fmaxf(v[j], 0.f);
        }
        if (BLEND) {
            const int rr[4] = { r0, r0, r0 + 8, r0 + 8 };
            const int cc[4] = { c0, c0 + 1, c0, c0 + 1 };
            #pragma unroll
            for (int j = 0; j < 4; j++) {
                float fv = __half2float(F[rr[j] * sf + cc[j]])
                         + __half2float(F[rr[j] * sf + fpl + cc[j]]);
                v[j] = v[j] * alpha + beta * fv;
            }
        }
        __half h0, l0, h1, l1, h2, l2, h3, l3;
        split2(v[0], h0, l0); split2(v[1], h1, l1);
        split2(v[2], h2, l2); split2(v[3], h3, l3);
        *(__half2*)(Bo + r0 * sb + c0)             = __halves2half2(h0, h1);
        *(__half2*)(Bo + r0 * sb + bpl + c0)       = __halves2half2(l0, l1);
        *(__half2*)(Bo + (r0 + 8) * sb + c0)       = __halves2half2(h2, h3);
        *(__half2*)(Bo + (r0 + 8) * sb + bpl + c0) = __halves2half2(l2, l3);
    }
    __syncwarp();
}

template <int KT, int NT, bool RELU>
__device__ __forceinline__ void gemm_s(const __half* A, int sa, int apl,
                                       const __half* W, int ws, int wpl,
                                       __half* Bo, int sb, int bpl)
{
    gemm_split<KT, NT, RELU, false>(A, sa, apl, W, ws, wpl, Bo, sb, bpl,
                                    nullptr, 0, 0, 0.f, 0.f);
}

// Convert fp32 weight [K x N] row-major to split fp16 planes (lo at +K*ws).
__device__ __forceinline__ void load_w_split(__half* dst, const float* __restrict__ src,
                                             int K, int N, int ws, int tid, int nt)
{
    const int tot = K * N / 2;
    const int pl  = K * ws;
    const float2* s2 = (const float2*)src;
    for (int i = tid; i < tot; i += nt) {
        int r = (2 * i) / N, c = (2 * i) % N;
        float2 v = s2[i];
        __half hx, lx, hy, ly;
        split2(v.x, hx, lx);
        split2(v.y, hy, ly);
        *(__half2*)(dst + r * ws + c)      = __halves2half2(hx, hy);
        *(__half2*)(dst + r * ws + pl + c) = __halves2half2(lx, ly);
    }
}

// ---------------------------------------------------------------------------
// Branch MLP: enc[32] -> 64(relu) x4 -> 64(linear) -> g_feat planes
// 256 threads = 8 warps, 128 points/block.  smem halves:
// ---------------------------------------------------------------------------
#define M_X     0
#define M_Y     (M_X + 128 * 72 * 2)
#define M_WIN   (M_Y + 128 * 72 * 2)
#define M_WH0   (M_WIN + 32 * 72 * 2)
#define M_WH1   (M_WH0 + 64 * 72 * 2)
#define M_WH2   (M_WH1 + 64 * 72 * 2)
#define M_WOUT  (M_WH2 + 64 * 72 * 2)
#define M_TOT   (M_WOUT + 64 * 72 * 2)
#define MLP64_SMEM (M_TOT * 2)
#define XPL (128 * 72)     // activation lo-plane offset

template <int WHICH>
__global__ void __launch_bounds__(256, 1)
mlp64_tc(const float* __restrict__ w_in,
         const float* __restrict__ w_hid,
         const float* __restrict__ w_out)
{
    extern __shared__ __align__(16) __half sm[];
    const int tid = threadIdx.x;
    const size_t blockbase = (size_t)blockIdx.x * 128;

    load_w_split(sm + M_WIN,  w_in,         32, 64, 72, tid, 256);
    load_w_split(sm + M_WH0,  w_hid + 0,    64, 64, 72, tid, 256);
    load_w_split(sm + M_WH1,  w_hid + 4096, 64, 64, 72, tid, 256);
    load_w_split(sm + M_WH2,  w_hid + 8192, 64, 64, 72, tid, 256);
    load_w_split(sm + M_WOUT, w_out,        64, 64, 72, tid, 256);

    {
        const __half2* ehi = (const __half2*)((WHICH == 0 ? g_enc_s_hi : g_enc_d_hi)
                                              + blockbase * 32);
        const __half2* elo = (const __half2*)((WHICH == 0 ? g_enc_s_lo : g_enc_d_lo)
                                              + blockbase * 32);
        for (int i = tid; i < 128 * 16; i += 256) {
            int row = i >> 4, c = i & 15;
            *(__half2*)(sm + M_X + row * 72 + 2 * c)       = ehi[i];
            *(__half2*)(sm + M_X + XPL + row * 72 + 2 * c) = elo[i];
        }
    }
    __syncthreads();

    const int w = tid >> 5;
    __half* X = sm + M_X + w * 16 * 72;
    __half* Y = sm + M_Y + w * 16 * 72;

    gemm_s<2, 8, true >(X, 72, XPL, sm + M_WIN,  72, 32 * 72, Y, 72, XPL);
    gemm_s<4, 8, true >(Y, 72, XPL, sm + M_WH0,  72, 64 * 72, X, 72, XPL);
    gemm_s<4, 8, true >(X, 72, XPL, sm + M_WH1,  72, 64 * 72, Y, 72, XPL);
    gemm_s<4, 8, true >(Y, 72, XPL, sm + M_WH2,  72, 64 * 72, X, 72, XPL);
    gemm_s<4, 8, false>(X, 72, XPL, sm + M_WOUT, 72, 64 * 72, Y, 72, XPL);

    const int lane = tid & 31;
    for (int i = lane; i < 16 * 32; i += 32) {
        int row = i >> 5, c = i & 31;
        size_t g = (blockbase + w * 16 + row) * 128 + WHICH * 64 + 2 * c;
        *(__half2*)(g_feat_hi + g) = *(__half2*)(Y + row * 72 + 2 * c);
        *(__half2*)(g_feat_lo + g) = *(__half2*)(Y + XPL + row * 72 + 2 * c);
    }
}

// ---------------------------------------------------------------------------
// Head: feat128 -> 64 -> 64 -> 128 (+blend fused) -> 64 -> 64 -> 1
// 128 threads = 4 warps, 64 points/block.  smem halves:
// ---------------------------------------------------------------------------
#define H_F     0
#define H_X     (H_F + 64 * 136 * 2)
#define H_Y     (H_X + 64 * 72 * 2)
#define H_W1IN  (H_Y + 64 * 72 * 2)
#define H_W1H   (H_W1IN + 128 * 72 * 2)
#define H_W1OUT (H_W1H + 64 * 72 * 2)
#define H_W2IN  (H_W1OUT + 64 * 136 * 2)
#define H_W2H   (H_W2IN + 128 * 72 * 2)
#define H_W2OUT (H_W2H + 64 * 72 * 2)     // 64 floats = 128 halves
#define H_TOT   (H_W2OUT + 128)
#define HEAD_SMEM (H_TOT * 2)
#define FPL (64 * 136)
#define HXPL (64 * 72)

__global__ void __launch_bounds__(128, 1)
head_tc(const float* __restrict__ alpha_p,
        const float* __restrict__ w1_in,
        const float* __restrict__ w1_hid,
        const float* __restrict__ w1_out,
        const float* __restrict__ w2_in,
        const float* __restrict__ w2_hid,
        const float* __restrict__ w2_out,
        float* __restrict__ out)
{
    extern __shared__ __align__(16) __half sm[];
    const int tid = threadIdx.x;
    const size_t blockbase = (size_t)blockIdx.x * 64;

    load_w_split(sm + H_W1IN,  w1_in,  128, 64,  72,  tid, 128);
    load_w_split(sm + H_W1H,   w1_hid, 64,  64,  72,  tid, 128);
    load_w_split(sm + H_W1OUT, w1_out, 64,  128, 136, tid, 128);
    load_w_split(sm + H_W2IN,  w2_in,  128, 64,  72,  tid, 128);
    load_w_split(sm + H_W2H,   w2_hid, 64,  64,  72,  tid, 128);
    {
        float* wo = (float*)(sm + H_W2OUT);
        for (int i = tid; i < 64; i += 128) wo[i] = w2_out[i];
    }

    {
        const __half2* fh = (const __half2*)(g_feat_hi + blockbase * 128);
        const __half2* fl = (const __half2*)(g_feat_lo + blockbase * 128);
        for (int i = tid; i < 64 * 64; i += 128) {
            int row = i >> 6, c = i & 63;
            *(__half2*)(sm + H_F + row * 136 + 2 * c)       = fh[i];
            *(__half2*)(sm + H_F + FPL + row * 136 + 2 * c) = fl[i];
        }
    }
    __syncthreads();

    const int w = tid >> 5;
    const int lane = tid & 31;
    __half* F = sm + H_F + w * 16 * 136;
    __half* X = sm + H_X + w * 16 * 72;
    __half* Y = sm + H_Y + w * 16 * 72;

    const float alpha = __ldg(alpha_p);
    const float beta  = 1.f - alpha;

    gemm_s<8, 8, true>(F, 136, FPL, sm + H_W1IN, 72, 128 * 72, X, 72, HXPL);
    gemm_s<4, 8, true>(X, 72, HXPL, sm + H_W1H,  72, 64 * 72,  Y, 72, HXPL);
    // w1_out with fused blend: F <- out1*alpha + (1-alpha)*F
    gemm_split<4, 16, false, true>(Y, 72, HXPL, sm + H_W1OUT, 136, 64 * 136,
                                   F, 136, FPL, F, 136, FPL, alpha, beta);

    gemm_s<8, 8, true>(F, 136, FPL, sm + H_W2IN, 72, 128 * 72, X, 72, HXPL);
    gemm_s<4, 8, true>(X, 72, HXPL, sm + H_W2H,  72, 64 * 72,  Y, 72, HXPL);

    // final 64 -> 1 in fp32 (reconstruct hi+lo)
    {
        const float* wo = (const float*)(sm + H_W2OUT);
        const int row = lane >> 1;
        const int kof = (lane & 1) * 32;
        float acc = 0.f;
        #pragma unroll
        for (int k = 0; k < 32; k++) {
            float v = __half2float(Y[row * 72 + kof + k])
                    + __half2float(Y[HXPL + row * 72 + kof + k]);
            acc = fmaf(v, wo[kof + k], acc);
        }
        acc += __shfl_xor_sync(0xffffffffu, acc, 1);
        if ((lane & 1) == 0)
            out[blockbase + w * 16 + row] = acc;
    }
}

// ---------------------------------------------------------------------------
// Launch
// ---------------------------------------------------------------------------
extern "C" void kernel_launch(void* const* d_in, const int* in_sizes, int n_in,
                              void* d_out, int out_size)
{
    const float* x       = (const float*)d_in[0];
    const float* t       = (const float*)d_in[1];
    const float* alpha   = (const float*)d_in[2];
    const float* table_s = (const float*)d_in[3];
    const float* ws_in   = (const float*)d_in[4];
    const float* ws_hid  = (const float*)d_in[5];
    const float* ws_out  = (const float*)d_in[6];
    const float* table_d = (const float*)d_in[7];
    const float* wd_in   = (const float*)d_in[8];
    const float* wd_hid  = (const float*)d_in[9];
    const float* wd_out  = (const float*)d_in[10];
    const float* w1_in   = (const float*)d_in[11];
    const float* w1_hid  = (const float*)d_in[12];
    const float* w1_out  = (const float*)d_in[13];
    const float* w2_in   = (const float*)d_in[14];
    const float* w2_hid  = (const float*)d_in[15];
    const float* w2_out  = (const float*)d_in[16];
    float* out = (float*)d_out;

    cudaFuncSetAttribute(mlp64_tc<0>, cudaFuncAttributeMaxDynamicSharedMemorySize, MLP64_SMEM);
    cudaFuncSetAttribute(mlp64_tc<1>, cudaFuncAttributeMaxDynamicSharedMemorySize, MLP64_SMEM);
    cudaFuncSetAttribute(head_tc,     cudaFuncAttributeMaxDynamicSharedMemorySize, HEAD_SMEM);

    const int nblk256 = NPTS / 256;
    const int nblkMLP = NPTS / 128;
    const int nblkHD  = NPTS / 64;

    encode_kernel<3, 0><<<nblk256, 256>>>(x, nullptr, table_s);
    encode_kernel<4, 1><<<nblk256, 256>>>(x, t,       table_d);

    mlp64_tc<0><<<nblkMLP, 256, MLP64_SMEM>>>(ws_in, ws_hid, ws_out);
    mlp64_tc<1><<<nblkMLP, 256, MLP64_SMEM>>>(wd_in, wd_hid, wd_out);

    head_tc<<<nblkHD, 128, HEAD_SMEM>>>(alpha, w1_in, w1_hid, w1_out,
                                        w2_in, w2_hid, w2_out, out);
}

// round 4
// speedup vs baseline: 1.7256x; 1.3803x over previous
#include <cuda_runtime.h>
#include <cuda_fp16.h>
#include <cstdint>

// ---------------------------------------------------------------------------
// Problem constants
// ---------------------------------------------------------------------------
#define NPTS   524288
#define LVLS   16
#define TSIZE  524288u
#define TMASK  (TSIZE - 1u)

__constant__ float c_res[LVLS] = {
    16.f, 24.f, 36.f, 54.f, 81.f, 121.f, 182.f, 273.f,
    410.f, 615.f, 922.f, 1383.f, 2075.f, 3113.f, 4670.f, 7006.f
};

// ---------------------------------------------------------------------------
// Scratch (device globals; no runtime allocation)
// ---------------------------------------------------------------------------
__device__ __align__(16) __half g_enc_s_hi[(size_t)NPTS * 32];
__device__ __align__(16) __half g_enc_s_lo[(size_t)NPTS * 32];
__device__ __align__(16) __half g_enc_d_hi[(size_t)NPTS * 32];
__device__ __align__(16) __half g_enc_d_lo[(size_t)NPTS * 32];
__device__ __align__(16) __half g_feat_hi [(size_t)NPTS * 128];
__device__ __align__(16) __half g_feat_lo [(size_t)NPTS * 128];

// Pre-split weight blobs (hi plane, lo plane at +rows*stride), stride 72/136
// mlp blob: WIN@0 (32x72x2) WH0@4608 WH1@13824 WH2@23040 WOUT@32256, tot 41472
#define WB_IN   0
#define WB_H0   4608
#define WB_H1   13824
#define WB_H2   23040
#define WB_OUT  32256
#define WB_TOT  41472
__device__ __align__(16) __half g_wS[WB_TOT];
__device__ __align__(16) __half g_wD[WB_TOT];
// head1 blob: W1IN@0 (128x72x2) W1H@18432 (64x72x2) W1OUT@27648 (64x136x2)
#define H1_IN   0
#define H1_H    18432
#define H1_OUT  27648
#define H1_TOT  45056
__device__ __align__(16) __half g_wH1[H1_TOT];
// head2 blob: W2IN@0 (128x72x2) W2H@18432 (64x72x2)
#define H2_IN   0
#define H2_H    18432
#define H2_TOT  27648
__device__ __align__(16) __half g_wH2[H2_TOT];

// ---------------------------------------------------------------------------
__device__ __forceinline__ void split2(float x, __half& h, __half& l) {
    h = __float2half_rn(x);
    l = __float2half_rn(x - __half2float(h));
}

// Convert fp32 [K x N] row-major -> split fp16 planes (lo at +K*ws), grid-stride
__device__ __forceinline__ void conv_w(__half* dst, const float* __restrict__ src,
                                       int K, int N, int ws, int t0, int nt)
{
    const int tot = K * N / 2;
    const int pl  = K * ws;
    const float2* s2 = (const float2*)src;
    for (int i = t0; i < tot; i += nt) {
        int r = (2 * i) / N, c = (2 * i) % N;
        float2 v = s2[i];
        __half hx, lx, hy, ly;
        split2(v.x, hx, lx);
        split2(v.y, hy, ly);
        *(__half2*)(dst + r * ws + c)      = __halves2half2(hx, hy);
        *(__half2*)(dst + r * ws + pl + c) = __halves2half2(lx, ly);
    }
}

__global__ void __launch_bounds__(256)
prep_weights(const float* __restrict__ ws_in, const float* __restrict__ ws_hid,
             const float* __restrict__ ws_out,
             const float* __restrict__ wd_in, const float* __restrict__ wd_hid,
             const float* __restrict__ wd_out,
             const float* __restrict__ w1_in, const float* __restrict__ w1_hid,
             const float* __restrict__ w1_out,
             const float* __restrict__ w2_in, const float* __restrict__ w2_hid)
{
    const int t0 = blockIdx.x * 256 + threadIdx.x;
    const int nt = gridDim.x * 256;
    conv_w(g_wS + WB_IN,  ws_in,         32, 64, 72, t0, nt);
    conv_w(g_wS + WB_H0,  ws_hid + 0,    64, 64, 72, t0, nt);
    conv_w(g_wS + WB_H1,  ws_hid + 4096, 64, 64, 72, t0, nt);
    conv_w(g_wS + WB_H2,  ws_hid + 8192, 64, 64, 72, t0, nt);
    conv_w(g_wS + WB_OUT, ws_out,        64, 64, 72, t0, nt);
    conv_w(g_wD + WB_IN,  wd_in,         32, 64, 72, t0, nt);
    conv_w(g_wD + WB_H0,  wd_hid + 0,    64, 64, 72, t0, nt);
    conv_w(g_wD + WB_H1,  wd_hid + 4096, 64, 64, 72, t0, nt);
    conv_w(g_wD + WB_H2,  wd_hid + 8192, 64, 64, 72, t0, nt);
    conv_w(g_wD + WB_OUT, wd_out,        64, 64, 72, t0, nt);
    conv_w(g_wH1 + H1_IN,  w1_in,  128, 64,  72,  t0, nt);
    conv_w(g_wH1 + H1_H,   w1_hid, 64,  64,  72,  t0, nt);
    conv_w(g_wH1 + H1_OUT, w1_out, 64,  128, 136, t0, nt);
    conv_w(g_wH2 + H2_IN,  w2_in,  128, 64,  72,  t0, nt);
    conv_w(g_wH2 + H2_H,   w2_hid, 64,  64,  72,  t0, nt);
}

// ---------------------------------------------------------------------------
// Hash-grid encode.  D=3 (static) or D=4 (dynamic).
// ---------------------------------------------------------------------------
template <int D, int WHICH>
__global__ void __launch_bounds__(256)
encode_kernel(const float* __restrict__ x,
              const float* __restrict__ tptr,
              const float* __restrict__ table)
{
    const int n = blockIdx.x * 256 + threadIdx.x;

    float p[4];
    p[0] = x[3 * n + 0];
    p[1] = x[3 * n + 1];
    p[2] = x[3 * n + 2];
    if (D == 4) p[3] = __ldg(tptr);

    __half2 ehi[16], elo[16];

    #pragma unroll
    for (int l = 0; l < LVLS; l++) {
        const float res = c_res[l];
        uint32_t h[4][2];
        float    w[4][2];
        #pragma unroll
        for (int d = 0; d < D; d++) {
            const uint32_t pr = (d == 0) ? 1u
                              : (d == 1) ? 2654435761u
                              : (d == 2) ? 805459861u
                                         : 3674653429u;
            float pos = p[d] * res;
            float p0f = floorf(pos);
            float fr  = pos - p0f;
            uint32_t p0 = (uint32_t)p0f;
            h[d][0] = p0 * pr;
            h[d][1] = (p0 + 1u) * pr;
            w[d][0] = 1.f - fr;
            w[d][1] = fr;
        }

        const float2* tl = (const float2*)table + (size_t)l * TSIZE;
        float f0 = 0.f, f1 = 0.f;
        #pragma unroll
        for (int c = 0; c < (1 << D); c++) {
            uint32_t hh = h[0][c & 1] ^ h[1][(c >> 1) & 1] ^ h[2][(c >> 2) & 1];
            float    ww = w[0][c & 1] * w[1][(c >> 1) & 1] * w[2][(c >> 2) & 1];
            if (D == 4) {
                hh ^= h[3][(c >> 3) & 1];
                ww *= w[3][(c >> 3) & 1];
            }
            float2 f = __ldg(tl + (hh & TMASK));
            f0 = fmaf(ww, f.x, f0);
            f1 = fmaf(ww, f.y, f1);
        }
        __half h0, l0, h1, l1;
        split2(f0, h0, l0);
        split2(f1, h1, l1);
        ehi[l] = __halves2half2(h0, h1);
        elo[l] = __halves2half2(l0, l1);
    }

    __half* dh = (WHICH == 0 ? g_enc_s_hi : g_enc_d_hi) + (size_t)n * 32;
    __half* dl = (WHICH == 0 ? g_enc_s_lo : g_enc_d_lo) + (size_t)n * 32;
    #pragma unroll
    for (int i = 0; i < 4; i++) ((uint4*)dh)[i] = ((const uint4*)ehi)[i];
    #pragma unroll
    for (int i = 0; i < 4; i++) ((uint4*)dl)[i] = ((const uint4*)elo)[i];
}

// ---------------------------------------------------------------------------
// Tensor-core primitives
// ---------------------------------------------------------------------------
__device__ __forceinline__ uint32_t smem_u32(const void* p) {
    return (uint32_t)__cvta_generic_to_shared(p);
}

__device__ __forceinline__ void ldsm_x4(uint32_t& r0, uint32_t& r1,
                                        uint32_t& r2, uint32_t& r3, uint32_t a) {
    asm volatile("ldmatrix.sync.aligned.m8n8.x4.shared.b16 {%0,%1,%2,%3}, [%4];"
                 : "=r"(r0), "=r"(r1), "=r"(r2), "=r"(r3) : "r"(a));
}

__device__ __forceinline__ void ldsm_x4_t(uint32_t& r0, uint32_t& r1,
                                          uint32_t& r2, uint32_t& r3, uint32_t a) {
    asm volatile("ldmatrix.sync.aligned.m8n8.x4.trans.shared.b16 {%0,%1,%2,%3}, [%4];"
                 : "=r"(r0), "=r"(r1), "=r"(r2), "=r"(r3) : "r"(a));
}

__device__ __forceinline__ void mma16816(float* c, const uint32_t* a,
                                         uint32_t b0, uint32_t b1) {
    asm volatile(
        "mma.sync.aligned.m16n8k16.row.col.f32.f16.f16.f32 "
        "{%0,%1,%2,%3}, {%4,%5,%6,%7}, {%8,%9}, {%0,%1,%2,%3};"
        : "+f"(c[0]), "+f"(c[1]), "+f"(c[2]), "+f"(c[3])
        : "r"(a[0]), "r"(a[1]), "r"(a[2]), "r"(a[3]), "r"(b0), "r"(b1));
}

// ---------------------------------------------------------------------------
// Split-fp16 warp GEMM, 2 M-tiles (32 rows/warp), in-place-safe.
//   C = A_hi W_hi + A_hi W_lo + A_lo W_hi   (fp32 accumulate)
// A: warp-private 32 rows, stride sa (halves), lo plane at +apl.
// W: stride ws, lo plane at +wpl, column offset noff.
// Bo: stride sb, lo plane at +bpl, columns written at +noff.
// BLEND: Bo element <- acc*alpha + beta*(Bo_hi+Bo_lo) (read-before-write per thread)
// ---------------------------------------------------------------------------
template <int KT, int NT, bool RELU, bool BLEND>
__device__ __forceinline__ void gemm2(const __half* A, int sa, int apl,
                                      const __half* W, int ws, int wpl, int noff,
                                      __half* Bo, int sb, int bpl,
                                      float alpha, float beta)
{
    asm volatile("" ::: "memory");
    const int lane = threadIdx.x & 31;
    float acc[2][NT][4];
    #pragma unroll
    for (int m = 0; m < 2; m++)
        #pragma unroll
        for (int t = 0; t < NT; t++)
            #pragma unroll
            for (int j = 0; j < 4; j++) acc[m][t][j] = 0.f;

    #pragma unroll
    for (int kk = 0; kk < KT; kk++) {
        uint32_t ah[2][4], al[2][4];
        #pragma unroll
        for (int m = 0; m < 2; m++) {
            const __half* ap = A + (m * 16 + (lane & 15)) * sa + kk * 16
                             + ((lane >> 4) << 3);
            ldsm_x4(ah[m][0], ah[m][1], ah[m][2], ah[m][3], smem_u32(ap));
            ldsm_x4(al[m][0], al[m][1], al[m][2], al[m][3], smem_u32(ap + apl));
        }
        #pragma unroll
        for (int nb = 0; nb < NT / 2; nb++) {
            const __half* wp = W + (kk * 16 + (lane & 7) + ((lane >> 3) & 1) * 8) * ws
                             + noff + nb * 16 + ((lane >> 4) << 3);
            uint32_t bh0, bh1, bh2, bh3, bl0, bl1, bl2, bl3;
            ldsm_x4_t(bh0, bh1, bh2, bh3, smem_u32(wp));
            ldsm_x4_t(bl0, bl1, bl2, bl3, smem_u32(wp + wpl));
            #pragma unroll
            for (int m = 0; m < 2; m++) {
                mma16816(acc[m][2 * nb + 0], ah[m], bh0, bh1);
                mma16816(acc[m][2 * nb + 0], ah[m], bl0, bl1);
                mma16816(acc[m][2 * nb + 0], al[m], bh0, bh1);
                mma16816(acc[m][2 * nb + 1], ah[m], bh2, bh3);
                mma16816(acc[m][2 * nb + 1], ah[m], bl2, bl3);
                mma16816(acc[m][2 * nb + 1], al[m], bh2, bh3);
            }
        }
    }

    __syncwarp();
    #pragma unroll
    for (int m = 0; m < 2; m++) {
        const int r0 = m * 16 + (lane >> 2);
        #pragma unroll
        for (int t = 0; t < NT; t++) {
            const int c0 = noff + t * 8 + (lane & 3) * 2;
            float v[4] = { acc[m][t][0], acc[m][t][1], acc[m][t][2], acc[m][t][3] };
            if (RELU) {
                #pragma unroll
                for (int j = 0; j < 4; j++) v[j] = fmaxf(v[j], 0.f);
            }
            if (BLEND) {
                const int rr[4] = { r0, r0, r0 + 8, r0 + 8 };
                const int cc[4] = { c0, c0 + 1, c0, c0 + 1 };
                #pragma unroll
                for (int j = 0; j < 4; j++) {
                    float fv = __half2float(Bo[rr[j] * sb + cc[j]])
                             + __half2float(Bo[rr[j] * sb + bpl + cc[j]]);
                    v[j] = v[j] * alpha + beta * fv;
                }
            }
            __half h0, l0, h1, l1, h2, l2, h3, l3;
            split2(v[0], h0, l0); split2(v[1], h1, l1);
            split2(v[2], h2, l2); split2(v[3], h3, l3);
            *(__half2*)(Bo + r0 * sb + c0)             = __halves2half2(h0, h1);
            *(__half2*)(Bo + r0 * sb + bpl + c0)       = __halves2half2(l0, l1);
            *(__half2*)(Bo + (r0 + 8) * sb + c0)       = __halves2half2(h2, h3);
            *(__half2*)(Bo + (r0 + 8) * sb + bpl + c0) = __halves2half2(l2, l3);
        }
    }
    __syncwarp();
    asm volatile("" ::: "memory");
}

// ---------------------------------------------------------------------------
// Branch MLP: 256 threads = 8 warps x 32 pts = 256 pts/block.
// smem: X act (256x72 x2 planes) + weight blob image
// ---------------------------------------------------------------------------
#define M_XPL   (256 * 72)
#define M_SMW   (256 * 72 * 2)
#define MLP64_SMEM ((M_SMW + WB_TOT) * 2)

template <int WHICH>
__global__ void __launch_bounds__(256, 1)
mlp64_tc()
{
    extern __shared__ __align__(16) __half sm[];
    const int tid = threadIdx.x;
    const size_t blockbase = (size_t)blockIdx.x * 256;

    // Copy pre-split weight blob (uint4)
    {
        const uint4* src = (const uint4*)(WHICH == 0 ? g_wS : g_wD);
        uint4* dst = (uint4*)(sm + M_SMW);
        #pragma unroll 4
        for (int i = tid; i < WB_TOT / 8; i += 256) dst[i] = src[i];
    }
    // Load encoded inputs (32 halves/pt, both planes)
    {
        const uint4* sh = (const uint4*)((WHICH == 0 ? g_enc_s_hi : g_enc_d_hi)
                                         + blockbase * 32);
        const uint4* sl = (const uint4*)((WHICH == 0 ? g_enc_s_lo : g_enc_d_lo)
                                         + blockbase * 32);
        for (int i = tid; i < 256 * 4; i += 256) {
            int row = i >> 2, c = (i & 3) << 3;
            *(uint4*)(sm + row * 72 + c)         = sh[i];
            *(uint4*)(sm + M_XPL + row * 72 + c) = sl[i];
        }
    }
    __syncthreads();

    const int w = tid >> 5;
    __half* X = sm + w * 32 * 72;
    const __half* W = sm + M_SMW;

    gemm2<2, 8, true,  false>(X, 72, M_XPL, W + WB_IN,  72, 32 * 72, 0, X, 72, M_XPL, 0.f, 0.f);
    gemm2<4, 8, true,  false>(X, 72, M_XPL, W + WB_H0,  72, 64 * 72, 0, X, 72, M_XPL, 0.f, 0.f);
    gemm2<4, 8, true,  false>(X, 72, M_XPL, W + WB_H1,  72, 64 * 72, 0, X, 72, M_XPL, 0.f, 0.f);
    gemm2<4, 8, true,  false>(X, 72, M_XPL, W + WB_H2,  72, 64 * 72, 0, X, 72, M_XPL, 0.f, 0.f);
    gemm2<4, 8, false, false>(X, 72, M_XPL, W + WB_OUT, 72, 64 * 72, 0, X, 72, M_XPL, 0.f, 0.f);

    // Store warp's 32x64 result to g_feat planes (uint4 = 8 halves)
    const int lane = tid & 31;
    for (int i = lane; i < 32 * 8; i += 32) {
        int row = i >> 3, c = (i & 7) << 3;
        size_t pt = blockbase + w * 32 + row;
        *(uint4*)(g_feat_hi + pt * 128 + WHICH * 64 + c) = *(const uint4*)(X + row * 72 + c);
        *(uint4*)(g_feat_lo + pt * 128 + WHICH * 64 + c) = *(const uint4*)(X + M_XPL + row * 72 + c);
    }
}

// ---------------------------------------------------------------------------
// head1: feat128 -> 64 -> 64 -> 128 (+blend fused); writes blended to g_feat
// 128 threads = 4 warps x 32 pts = 128 pts/block.
// ---------------------------------------------------------------------------
#define HD_FPL  (128 * 136)
#define HD_X    (128 * 136 * 2)
#define HD_XPL  (128 * 72)
#define HD_W    (HD_X + 128 * 72 * 2)
#define HEAD1_SMEM ((HD_W + H1_TOT) * 2)
#define HEAD2_SMEM ((HD_W + H2_TOT + 128) * 2)

__global__ void __launch_bounds__(128, 1)
head1_tc(const float* __restrict__ alpha_p)
{
    extern __shared__ __align__(16) __half sm[];
    const int tid = threadIdx.x;
    const size_t blockbase = (size_t)blockIdx.x * 128;

    {
        const uint4* src = (const uint4*)g_wH1;
        uint4* dst = (uint4*)(sm + HD_W);
        #pragma unroll 4
        for (int i = tid; i < H1_TOT / 8; i += 128) dst[i] = src[i];
    }
    {
        const uint4* fh = (const uint4*)(g_feat_hi + blockbase * 128);
        const uint4* fl = (const uint4*)(g_feat_lo + blockbase * 128);
        for (int i = tid; i < 128 * 16; i += 128) {
            int row = i >> 4, c = (i & 15) << 3;
            *(uint4*)(sm + row * 136 + c)          = fh[i];
            *(uint4*)(sm + HD_FPL + row * 136 + c) = fl[i];
        }
    }
    __syncthreads();

    const int w = tid >> 5;
    __half* F = sm + w * 32 * 136;
    __half* X = sm + HD_X + w * 32 * 72;
    const __half* W = sm + HD_W;

    const float alpha = __ldg(alpha_p);
    const float beta  = 1.f - alpha;

    gemm2<8, 8, true, false>(F, 136, HD_FPL, W + H1_IN, 72, 128 * 72, 0, X, 72, HD_XPL, 0.f, 0.f);
    gemm2<4, 8, true, false>(X, 72, HD_XPL,  W + H1_H,  72, 64 * 72,  0, X, 72, HD_XPL, 0.f, 0.f);
    // w1_out (64->128) with fused blend into F, two 64-col halves
    gemm2<4, 8, false, true>(X, 72, HD_XPL, W + H1_OUT, 136, 64 * 136, 0,  F, 136, HD_FPL, alpha, beta);
    gemm2<4, 8, false, true>(X, 72, HD_XPL, W + H1_OUT, 136, 64 * 136, 64, F, 136, HD_FPL, alpha, beta);

    // Write blended features back to g_feat
    const int lane = tid & 31;
    for (int i = lane; i < 32 * 16; i += 32) {
        int row = i >> 4, c = (i & 15) << 3;
        size_t pt = blockbase + w * 32 + row;
        *(uint4*)(g_feat_hi + pt * 128 + c) = *(const uint4*)(F + row * 136 + c);
        *(uint4*)(g_feat_lo + pt * 128 + c) = *(const uint4*)(F + HD_FPL + row * 136 + c);
    }
}

// ---------------------------------------------------------------------------
// head2: blended128 -> 64 -> 64 -> 1
// ---------------------------------------------------------------------------
__global__ void __launch_bounds__(128, 1)
head2_tc(const float* __restrict__ w2_out, float* __restrict__ out)
{
    extern __shared__ __align__(16) __half sm[];
    const int tid = threadIdx.x;
    const size_t blockbase = (size_t)blockIdx.x * 128;
    float* wo = (float*)(sm + HD_W + H2_TOT);   // 64 floats

    {
        const uint4* src = (const uint4*)g_wH2;
        uint4* dst = (uint4*)(sm + HD_W);
        #pragma unroll 4
        for (int i = tid; i < H2_TOT / 8; i += 128) dst[i] = src[i];
        for (int i = tid; i < 64; i += 128) wo[i] = w2_out[i];
    }
    {
        const uint4* fh = (const uint4*)(g_feat_hi + blockbase * 128);
        const uint4* fl = (const uint4*)(g_feat_lo + blockbase * 128);
        for (int i = tid; i < 128 * 16; i += 128) {
            int row = i >> 4, c = (i & 15) << 3;
            *(uint4*)(sm + row * 136 + c)          = fh[i];
            *(uint4*)(sm + HD_FPL + row * 136 + c) = fl[i];
        }
    }
    __syncthreads();

    const int w = tid >> 5;
    const int lane = tid & 31;
    __half* F = sm + w * 32 * 136;
    __half* X = sm + HD_X + w * 32 * 72;
    const __half* W = sm + HD_W;

    gemm2<8, 8, true, false>(F, 136, HD_FPL, W + H2_IN, 72, 128 * 72, 0, X, 72, HD_XPL, 0.f, 0.f);
    gemm2<4, 8, true, false>(X, 72, HD_XPL,  W + H2_H,  72, 64 * 72,  0, X, 72, HD_XPL, 0.f, 0.f);

    // final 64 -> 1 in fp32 (one row per lane)
    float acc = 0.f;
    #pragma unroll
    for (int k = 0; k < 64; k++) {
        float v = __half2float(X[lane * 72 + k])
                + __half2float(X[HD_XPL + lane * 72 + k]);
        acc = fmaf(v, wo[k], acc);
    }
    out[blockbase + w * 32 + lane] = acc;
}

// ---------------------------------------------------------------------------
// Launch
// ---------------------------------------------------------------------------
extern "C" void kernel_launch(void* const* d_in, const int* in_sizes, int n_in,
                              void* d_out, int out_size)
{
    const float* x       = (const float*)d_in[0];
    const float* t       = (const float*)d_in[1];
    const float* alpha   = (const float*)d_in[2];
    const float* table_s = (const float*)d_in[3];
    const float* ws_in   = (const float*)d_in[4];
    const float* ws_hid  = (const float*)d_in[5];
    const float* ws_out  = (const float*)d_in[6];
    const float* table_d = (const float*)d_in[7];
    const float* wd_in   = (const float*)d_in[8];
    const float* wd_hid  = (const float*)d_in[9];
    const float* wd_out  = (const float*)d_in[10];
    const float* w1_in   = (const float*)d_in[11];
    const float* w1_hid  = (const float*)d_in[12];
    const float* w1_out  = (const float*)d_in[13];
    const float* w2_in   = (const float*)d_in[14];
    const float* w2_hid  = (const float*)d_in[15];
    const float* w2_out  = (const float*)d_in[16];
    float* out = (float*)d_out;

    cudaFuncSetAttribute(mlp64_tc<0>, cudaFuncAttributeMaxDynamicSharedMemorySize, MLP64_SMEM);
    cudaFuncSetAttribute(mlp64_tc<1>, cudaFuncAttributeMaxDynamicSharedMemorySize, MLP64_SMEM);
    cudaFuncSetAttribute(head1_tc,    cudaFuncAttributeMaxDynamicSharedMemorySize, HEAD1_SMEM);
    cudaFuncSetAttribute(head2_tc,    cudaFuncAttributeMaxDynamicSharedMemorySize, HEAD2_SMEM);

    prep_weights<<<64, 256>>>(ws_in, ws_hid, ws_out, wd_in, wd_hid, wd_out,
                              w1_in, w1_hid, w1_out, w2_in, w2_hid);

    const int nblkENC = NPTS / 256;
    const int nblkMLP = NPTS / 256;
    const int nblkHD  = NPTS / 128;

    encode_kernel<3, 0><<<nblkENC, 256>>>(x, nullptr, table_s);
    encode_kernel<4, 1><<<nblkENC, 256>>>(x, t,       table_d);

    mlp64_tc<0><<<nblkMLP, 256, MLP64_SMEM>>>();
    mlp64_tc<1><<<nblkMLP, 256, MLP64_SMEM>>>();

    head1_tc<<<nblkHD, 128, HEAD1_SMEM>>>(alpha);
    head2_tc<<<nblkHD, 128, HEAD2_SMEM>>>(w2_out, out);
}